// round 1
// baseline (speedup 1.0000x reference)
#include <cuda_runtime.h>

// SpatialTransformer3D: B=4, vol 128^3, C=2, resampled 128^3.
// One thread per output point. float2 gathers (C=2) + float2 store.

#define B_  4
#define R_  128            // r0 = r1 = r2 = H = W = D = 128
#define R3_ (128*128*128)
#define NPTS (B_ * R3_)    // 8,388,608

__device__ __forceinline__ int clampi(int v, int lo, int hi) {
    return v < lo ? lo : (v > hi ? hi : v);
}

__global__ __launch_bounds__(256)
void st3d_kernel(const float* __restrict__ images,
                 const float* __restrict__ params,
                 float2* __restrict__ out)
{
    int p = blockIdx.x * blockDim.x + threadIdx.x;
    if (p >= NPTS) return;

    int i2 = p & 127;            // -> z
    int i1 = (p >> 7) & 127;     // -> x
    int i0 = (p >> 14) & 127;    // -> y
    int b  = p >> 21;

    const float step = 2.0f / 127.0f;
    float xn = fmaf((float)i1, step, -1.0f);
    float yn = fmaf((float)i0, step, -1.0f);
    float zn = fmaf((float)i2, step, -1.0f);

    const float* m = params + b * 12;
    float m00 = __ldg(m+0),  m01 = __ldg(m+1),  m02 = __ldg(m+2),  m03 = __ldg(m+3);
    float m10 = __ldg(m+4),  m11 = __ldg(m+5),  m12 = __ldg(m+6),  m13 = __ldg(m+7);
    float m20 = __ldg(m+8),  m21 = __ldg(m+9),  m22 = __ldg(m+10), m23 = __ldg(m+11);

    float sgx = fmaf(m00, xn, fmaf(m01, yn, fmaf(m02, zn, m03)));
    float sgy = fmaf(m10, xn, fmaf(m11, yn, fmaf(m12, zn, m13)));
    float sgz = fmaf(m20, xn, fmaf(m21, yn, fmaf(m22, zn, m23)));

    // 0.5 * (sg + 1) * 128
    float x = (sgx + 1.0f) * 64.0f;
    float y = (sgy + 1.0f) * 64.0f;
    float z = (sgz + 1.0f) * 64.0f;

    int xi = (int)x;  // trunc toward zero, matches jnp astype(int32)
    int yi = (int)y;
    int zi = (int)z;

    int x0 = clampi(xi,     0, 127);
    int x1 = clampi(xi + 1, 0, 127);
    int y0 = clampi(yi,     0, 127);
    int y1 = clampi(yi + 1, 0, 127);
    int z0 = clampi(zi,     0, 127);
    int z1 = clampi(zi + 1, 0, 127);

    float x0f = (float)x0, x1f = (float)x1;
    float y0f = (float)y0, y1f = (float)y1;
    float z0f = (float)z0, z1f = (float)z1;

    float wx0 = x1f - x, wx1 = x - x0f;
    float wy0 = y1f - y, wy1 = y - y0f;
    float wz0 = z1f - z, wz1 = z - z0f;

    // flat index = z*(W*H) + y*W + x  (reference's transposed addressing)
    const float2* vol = (const float2*)images + (size_t)b * R3_;

    int iz0 = z0 << 14, iz1 = z1 << 14;
    int iy0 = y0 << 7,  iy1 = y1 << 7;

    float2 c000 = __ldg(vol + iz0 + iy0 + x0);
    float2 c100 = __ldg(vol + iz1 + iy0 + x0);
    float2 c010 = __ldg(vol + iz0 + iy1 + x0);
    float2 c110 = __ldg(vol + iz1 + iy1 + x0);
    float2 c001 = __ldg(vol + iz0 + iy0 + x1);
    float2 c101 = __ldg(vol + iz1 + iy0 + x1);
    float2 c011 = __ldg(vol + iz0 + iy1 + x1);
    float2 c111 = __ldg(vol + iz1 + iy1 + x1);

    float w000 = wx0 * wy0 * wz0;
    float w100 = wx0 * wy0 * wz1;
    float w010 = wx0 * wy1 * wz0;
    float w110 = wx0 * wy1 * wz1;
    float w001 = wx1 * wy0 * wz0;
    float w101 = wx1 * wy0 * wz1;
    float w011 = wx1 * wy1 * wz0;
    float w111 = wx1 * wy1 * wz1;

    float2 acc;
    acc.x = w000 * c000.x;
    acc.y = w000 * c000.y;
    acc.x = fmaf(w100, c100.x, acc.x);
    acc.y = fmaf(w100, c100.y, acc.y);
    acc.x = fmaf(w010, c010.x, acc.x);
    acc.y = fmaf(w010, c010.y, acc.y);
    acc.x = fmaf(w110, c110.x, acc.x);
    acc.y = fmaf(w110, c110.y, acc.y);
    acc.x = fmaf(w001, c001.x, acc.x);
    acc.y = fmaf(w001, c001.y, acc.y);
    acc.x = fmaf(w101, c101.x, acc.x);
    acc.y = fmaf(w101, c101.y, acc.y);
    acc.x = fmaf(w011, c011.x, acc.x);
    acc.y = fmaf(w011, c011.y, acc.y);
    acc.x = fmaf(w111, c111.x, acc.x);
    acc.y = fmaf(w111, c111.y, acc.y);

    out[p] = acc;
}

extern "C" void kernel_launch(void* const* d_in, const int* in_sizes, int n_in,
                              void* d_out, int out_size)
{
    const float* images = (const float*)d_in[0];
    const float* params = (const float*)d_in[1];
    float2* out = (float2*)d_out;

    dim3 block(256);
    dim3 grid(NPTS / 256);
    st3d_kernel<<<grid, block>>>(images, params, out);
}

// round 2
// speedup vs baseline: 3.8182x; 3.8182x over previous
#include <cuda_runtime.h>

// SpatialTransformer3D: B=4, vol 128^3, C=2, resampled 128^3.
// Tile 32(i1) x 32(i2) per block. Gather phase: lanes vary along i1 so the
// 8 trilinear corner gathers (addr = z*16384 + y*128 + x, float2 units) are
// unit-stride within a warp. Results staged in padded smem, then stored with
// lanes varying along i2 (unit-stride output).

#define R3_ (128*128*128)

__device__ __forceinline__ int clampi(int v, int lo, int hi) {
    return v < lo ? lo : (v > hi ? hi : v);
}

__global__ __launch_bounds__(256)
void st3d_kernel(const float* __restrict__ images,
                 const float* __restrict__ params,
                 float2* __restrict__ out)
{
    __shared__ float2 tile[32][33];   // [i2_local][i1_local], pad to break conflicts

    int t    = threadIdx.x;
    int lane = t & 31;
    int warp = t >> 5;

    int blk = blockIdx.x;
    int i2t = (blk & 3) << 5;         // i2 tile base
    int i1t = ((blk >> 2) & 3) << 5;  // i1 tile base
    int i0  = (blk >> 4) & 127;
    int b   = blk >> 11;

    const float* m = params + b * 12;
    float m00 = __ldg(m+0),  m01 = __ldg(m+1),  m02 = __ldg(m+2),  m03 = __ldg(m+3);
    float m10 = __ldg(m+4),  m11 = __ldg(m+5),  m12 = __ldg(m+6),  m13 = __ldg(m+7);
    float m20 = __ldg(m+8),  m21 = __ldg(m+9),  m22 = __ldg(m+10), m23 = __ldg(m+11);

    const float step = 2.0f / 127.0f;

    // ---- gather phase: lane -> i1, warp*4+j -> i2 ----
    int i1 = i1t + lane;
    float xn = fmaf((float)i1, step, -1.0f);
    float yn = fmaf((float)i0, step, -1.0f);

    // z-independent parts of the affine transform
    float bx = fmaf(m00, xn, fmaf(m01, yn, m03));
    float by = fmaf(m10, xn, fmaf(m11, yn, m13));
    float bz = fmaf(m20, xn, fmaf(m21, yn, m23));

    const float2* vol = (const float2*)images + (size_t)b * R3_;

    #pragma unroll
    for (int j = 0; j < 4; j++) {
        int i2l = (warp << 2) + j;
        int i2  = i2t + i2l;
        float zn = fmaf((float)i2, step, -1.0f);

        float x = (fmaf(m02, zn, bx) + 1.0f) * 64.0f;
        float y = (fmaf(m12, zn, by) + 1.0f) * 64.0f;
        float z = (fmaf(m22, zn, bz) + 1.0f) * 64.0f;

        int xi = (int)x, yi = (int)y, zi = (int)z;  // trunc toward zero
        int x0 = clampi(xi,     0, 127);
        int x1 = clampi(xi + 1, 0, 127);
        int y0 = clampi(yi,     0, 127);
        int y1 = clampi(yi + 1, 0, 127);
        int z0 = clampi(zi,     0, 127);
        int z1 = clampi(zi + 1, 0, 127);

        float wx0 = (float)x1 - x, wx1 = x - (float)x0;
        float wy0 = (float)y1 - y, wy1 = y - (float)y0;
        float wz0 = (float)z1 - z, wz1 = z - (float)z0;

        int iz0 = z0 << 14, iz1 = z1 << 14;
        int iy0 = y0 << 7,  iy1 = y1 << 7;

        float2 c000 = __ldg(vol + iz0 + iy0 + x0);
        float2 c100 = __ldg(vol + iz1 + iy0 + x0);
        float2 c010 = __ldg(vol + iz0 + iy1 + x0);
        float2 c110 = __ldg(vol + iz1 + iy1 + x0);
        float2 c001 = __ldg(vol + iz0 + iy0 + x1);
        float2 c101 = __ldg(vol + iz1 + iy0 + x1);
        float2 c011 = __ldg(vol + iz0 + iy1 + x1);
        float2 c111 = __ldg(vol + iz1 + iy1 + x1);

        float w000 = wx0 * wy0 * wz0;
        float w100 = wx0 * wy0 * wz1;
        float w010 = wx0 * wy1 * wz0;
        float w110 = wx0 * wy1 * wz1;
        float w001 = wx1 * wy0 * wz0;
        float w101 = wx1 * wy0 * wz1;
        float w011 = wx1 * wy1 * wz0;
        float w111 = wx1 * wy1 * wz1;

        float2 acc;
        acc.x = w000 * c000.x;
        acc.y = w000 * c000.y;
        acc.x = fmaf(w100, c100.x, acc.x);  acc.y = fmaf(w100, c100.y, acc.y);
        acc.x = fmaf(w010, c010.x, acc.x);  acc.y = fmaf(w010, c010.y, acc.y);
        acc.x = fmaf(w110, c110.x, acc.x);  acc.y = fmaf(w110, c110.y, acc.y);
        acc.x = fmaf(w001, c001.x, acc.x);  acc.y = fmaf(w001, c001.y, acc.y);
        acc.x = fmaf(w101, c101.x, acc.x);  acc.y = fmaf(w101, c101.y, acc.y);
        acc.x = fmaf(w011, c011.x, acc.x);  acc.y = fmaf(w011, c011.y, acc.y);
        acc.x = fmaf(w111, c111.x, acc.x);  acc.y = fmaf(w111, c111.y, acc.y);

        tile[i2l][lane] = acc;
    }

    __syncthreads();

    // ---- store phase: lane -> i2 (unit stride in output), warp+8j -> i1 ----
    size_t out_base = ((size_t)b << 21) + ((size_t)i0 << 14);
    #pragma unroll
    for (int j = 0; j < 4; j++) {
        int i1l = warp + (j << 3);
        int i2l = lane;
        float2 v = tile[i2l][i1l];
        out[out_base + (size_t)(i1t + i1l) * 128 + (i2t + i2l)] = v;
    }
}

extern "C" void kernel_launch(void* const* d_in, const int* in_sizes, int n_in,
                              void* d_out, int out_size)
{
    const float* images = (const float*)d_in[0];
    const float* params = (const float*)d_in[1];
    float2* out = (float2*)d_out;

    // blocks: 4(i2 tiles) * 4(i1 tiles) * 128(i0) * 4(b) = 8192
    st3d_kernel<<<8192, 256>>>(images, params, out);
}

// round 3
// speedup vs baseline: 4.1593x; 1.0893x over previous
#include <cuda_runtime.h>

// SpatialTransformer3D: B=4, vol 128^3, C=2, resampled 128^3.
// Tile 32(i1) x 32(i2) per block; lanes along i1 for coalesced gathers,
// smem transpose for coalesced stores along i2.
// R3: batch TWO i2-steps per loop body — issue all 16 gathers before either
// epilogue so the memory latency of batch j overlaps with batch j+1.

#define R3_ (128*128*128)

__device__ __forceinline__ int clampi(int v, int lo, int hi) {
    return v < lo ? lo : (v > hi ? hi : v);
}

struct Corner {
    int x0, x1;
    int r00, r01, r10, r11;   // row offsets: iz+iy combos (float2 units)
    float wx0, wx1, wy0, wy1, wz0, wz1;
};

__device__ __forceinline__ Corner make_corner(float x, float y, float z) {
    Corner c;
    int xi = (int)x, yi = (int)y, zi = (int)z;   // trunc toward zero
    c.x0 = clampi(xi,     0, 127);
    c.x1 = clampi(xi + 1, 0, 127);
    int y0 = clampi(yi,     0, 127);
    int y1 = clampi(yi + 1, 0, 127);
    int z0 = clampi(zi,     0, 127);
    int z1 = clampi(zi + 1, 0, 127);
    c.wx0 = (float)c.x1 - x;  c.wx1 = x - (float)c.x0;
    c.wy0 = (float)y1   - y;  c.wy1 = y - (float)y0;
    c.wz0 = (float)z1   - z;  c.wz1 = z - (float)z0;
    int iz0 = z0 << 14, iz1 = z1 << 14;
    int iy0 = y0 << 7,  iy1 = y1 << 7;
    c.r00 = iz0 + iy0;  c.r01 = iz0 + iy1;
    c.r10 = iz1 + iy0;  c.r11 = iz1 + iy1;
    return c;
}

__device__ __forceinline__ float2 lerp8(const Corner& c,
    float2 c000, float2 c001, float2 c010, float2 c011,
    float2 c100, float2 c101, float2 c110, float2 c111)
{
    float wxy00 = c.wx0 * c.wy0;
    float wxy01 = c.wx0 * c.wy1;
    float wxy10 = c.wx1 * c.wy0;
    float wxy11 = c.wx1 * c.wy1;
    float w000 = wxy00 * c.wz0, w100 = wxy00 * c.wz1;
    float w010 = wxy01 * c.wz0, w110 = wxy01 * c.wz1;
    float w001 = wxy10 * c.wz0, w101 = wxy10 * c.wz1;
    float w011 = wxy11 * c.wz0, w111 = wxy11 * c.wz1;

    float2 acc;
    acc.x = w000 * c000.x;                 acc.y = w000 * c000.y;
    acc.x = fmaf(w100, c100.x, acc.x);     acc.y = fmaf(w100, c100.y, acc.y);
    acc.x = fmaf(w010, c010.x, acc.x);     acc.y = fmaf(w010, c010.y, acc.y);
    acc.x = fmaf(w110, c110.x, acc.x);     acc.y = fmaf(w110, c110.y, acc.y);
    acc.x = fmaf(w001, c001.x, acc.x);     acc.y = fmaf(w001, c001.y, acc.y);
    acc.x = fmaf(w101, c101.x, acc.x);     acc.y = fmaf(w101, c101.y, acc.y);
    acc.x = fmaf(w011, c011.x, acc.x);     acc.y = fmaf(w011, c011.y, acc.y);
    acc.x = fmaf(w111, c111.x, acc.x);     acc.y = fmaf(w111, c111.y, acc.y);
    return acc;
}

__global__ __launch_bounds__(256, 4)
void st3d_kernel(const float* __restrict__ images,
                 const float* __restrict__ params,
                 float2* __restrict__ out)
{
    __shared__ float2 tile[32][33];

    int t    = threadIdx.x;
    int lane = t & 31;
    int warp = t >> 5;

    int blk = blockIdx.x;
    int i2t = (blk & 3) << 5;
    int i1t = ((blk >> 2) & 3) << 5;
    int i0  = (blk >> 4) & 127;
    int b   = blk >> 11;

    const float* m = params + b * 12;
    float m00 = __ldg(m+0),  m01 = __ldg(m+1),  m02 = __ldg(m+2),  m03 = __ldg(m+3);
    float m10 = __ldg(m+4),  m11 = __ldg(m+5),  m12 = __ldg(m+6),  m13 = __ldg(m+7);
    float m20 = __ldg(m+8),  m21 = __ldg(m+9),  m22 = __ldg(m+10), m23 = __ldg(m+11);

    const float step = 2.0f / 127.0f;
    int i1 = i1t + lane;
    float xn = fmaf((float)i1, step, -1.0f);
    float yn = fmaf((float)i0, step, -1.0f);

    // z-independent parts; fold the (v+1)*64 scale in as fmaf at the end
    float bx = fmaf(m00, xn, fmaf(m01, yn, m03));
    float by = fmaf(m10, xn, fmaf(m11, yn, m13));
    float bz = fmaf(m20, xn, fmaf(m21, yn, m23));

    const float2* __restrict__ vol = (const float2*)images + (size_t)b * R3_;

    int i2base = i2t + (warp << 2);

    #pragma unroll
    for (int jj = 0; jj < 2; jj++) {
        int jA = jj * 2;
        int jB = jA + 1;

        float znA = fmaf((float)(i2base + jA), step, -1.0f);
        float znB = fmaf((float)(i2base + jB), step, -1.0f);

        float xA = fmaf(fmaf(m02, znA, bx), 64.0f, 64.0f);
        float yA = fmaf(fmaf(m12, znA, by), 64.0f, 64.0f);
        float zA = fmaf(fmaf(m22, znA, bz), 64.0f, 64.0f);
        float xB = fmaf(fmaf(m02, znB, bx), 64.0f, 64.0f);
        float yB = fmaf(fmaf(m12, znB, by), 64.0f, 64.0f);
        float zB = fmaf(fmaf(m22, znB, bz), 64.0f, 64.0f);

        Corner A = make_corner(xA, yA, zA);
        Corner B = make_corner(xB, yB, zB);

        // Issue all 16 gathers before any consumption (max MLP)
        float2 a000 = __ldg(vol + A.r00 + A.x0);
        float2 a100 = __ldg(vol + A.r10 + A.x0);
        float2 a010 = __ldg(vol + A.r01 + A.x0);
        float2 a110 = __ldg(vol + A.r11 + A.x0);
        float2 a001 = __ldg(vol + A.r00 + A.x1);
        float2 a101 = __ldg(vol + A.r10 + A.x1);
        float2 a011 = __ldg(vol + A.r01 + A.x1);
        float2 a111 = __ldg(vol + A.r11 + A.x1);

        float2 b000 = __ldg(vol + B.r00 + B.x0);
        float2 b100 = __ldg(vol + B.r10 + B.x0);
        float2 b010 = __ldg(vol + B.r01 + B.x0);
        float2 b110 = __ldg(vol + B.r11 + B.x0);
        float2 b001 = __ldg(vol + B.r00 + B.x1);
        float2 b101 = __ldg(vol + B.r10 + B.x1);
        float2 b011 = __ldg(vol + B.r01 + B.x1);
        float2 b111 = __ldg(vol + B.r11 + B.x1);

        tile[(warp << 2) + jA][lane] =
            lerp8(A, a000, a001, a010, a011, a100, a101, a110, a111);
        tile[(warp << 2) + jB][lane] =
            lerp8(B, b000, b001, b010, b011, b100, b101, b110, b111);
    }

    __syncthreads();

    size_t out_base = ((size_t)b << 21) + ((size_t)i0 << 14);
    #pragma unroll
    for (int j = 0; j < 4; j++) {
        int i1l = warp + (j << 3);
        float2 v = tile[lane][i1l];
        out[out_base + (size_t)(i1t + i1l) * 128 + (i2t + lane)] = v;
    }
}

extern "C" void kernel_launch(void* const* d_in, const int* in_sizes, int n_in,
                              void* d_out, int out_size)
{
    const float* images = (const float*)d_in[0];
    const float* params = (const float*)d_in[1];
    float2* out = (float2*)d_out;

    st3d_kernel<<<8192, 256>>>(images, params, out);
}

// round 4
// speedup vs baseline: 4.2906x; 1.0316x over previous
#include <cuda_runtime.h>

// SpatialTransformer3D: B=4, vol 128^3, C=2, resampled 128^3.
// Tile 32(i1) x 32(i2) per block; lanes along i1 for coalesced gathers,
// smem transpose for coalesced stores along i2.
// R3: batch TWO i2-steps per loop body — issue all 16 gathers before either
// epilogue so the memory latency of batch j overlaps with batch j+1.

#define R3_ (128*128*128)

__device__ __forceinline__ int clampi(int v, int lo, int hi) {
    return v < lo ? lo : (v > hi ? hi : v);
}

struct Corner {
    int x0, x1;
    int r00, r01, r10, r11;   // row offsets: iz+iy combos (float2 units)
    float wx0, wx1, wy0, wy1, wz0, wz1;
};

__device__ __forceinline__ Corner make_corner(float x, float y, float z) {
    Corner c;
    int xi = (int)x, yi = (int)y, zi = (int)z;   // trunc toward zero
    c.x0 = clampi(xi,     0, 127);
    c.x1 = clampi(xi + 1, 0, 127);
    int y0 = clampi(yi,     0, 127);
    int y1 = clampi(yi + 1, 0, 127);
    int z0 = clampi(zi,     0, 127);
    int z1 = clampi(zi + 1, 0, 127);
    c.wx0 = (float)c.x1 - x;  c.wx1 = x - (float)c.x0;
    c.wy0 = (float)y1   - y;  c.wy1 = y - (float)y0;
    c.wz0 = (float)z1   - z;  c.wz1 = z - (float)z0;
    int iz0 = z0 << 14, iz1 = z1 << 14;
    int iy0 = y0 << 7,  iy1 = y1 << 7;
    c.r00 = iz0 + iy0;  c.r01 = iz0 + iy1;
    c.r10 = iz1 + iy0;  c.r11 = iz1 + iy1;
    return c;
}

__device__ __forceinline__ float2 lerp8(const Corner& c,
    float2 c000, float2 c001, float2 c010, float2 c011,
    float2 c100, float2 c101, float2 c110, float2 c111)
{
    float wxy00 = c.wx0 * c.wy0;
    float wxy01 = c.wx0 * c.wy1;
    float wxy10 = c.wx1 * c.wy0;
    float wxy11 = c.wx1 * c.wy1;
    float w000 = wxy00 * c.wz0, w100 = wxy00 * c.wz1;
    float w010 = wxy01 * c.wz0, w110 = wxy01 * c.wz1;
    float w001 = wxy10 * c.wz0, w101 = wxy10 * c.wz1;
    float w011 = wxy11 * c.wz0, w111 = wxy11 * c.wz1;

    float2 acc;
    acc.x = w000 * c000.x;                 acc.y = w000 * c000.y;
    acc.x = fmaf(w100, c100.x, acc.x);     acc.y = fmaf(w100, c100.y, acc.y);
    acc.x = fmaf(w010, c010.x, acc.x);     acc.y = fmaf(w010, c010.y, acc.y);
    acc.x = fmaf(w110, c110.x, acc.x);     acc.y = fmaf(w110, c110.y, acc.y);
    acc.x = fmaf(w001, c001.x, acc.x);     acc.y = fmaf(w001, c001.y, acc.y);
    acc.x = fmaf(w101, c101.x, acc.x);     acc.y = fmaf(w101, c101.y, acc.y);
    acc.x = fmaf(w011, c011.x, acc.x);     acc.y = fmaf(w011, c011.y, acc.y);
    acc.x = fmaf(w111, c111.x, acc.x);     acc.y = fmaf(w111, c111.y, acc.y);
    return acc;
}

__global__ __launch_bounds__(256, 4)
void st3d_kernel(const float* __restrict__ images,
                 const float* __restrict__ params,
                 float2* __restrict__ out)
{
    __shared__ float2 tile[32][33];

    int t    = threadIdx.x;
    int lane = t & 31;
    int warp = t >> 5;

    int blk = blockIdx.x;
    int i2t = (blk & 3) << 5;
    int i1t = ((blk >> 2) & 3) << 5;
    int i0  = (blk >> 4) & 127;
    int b   = blk >> 11;

    const float* m = params + b * 12;
    float m00 = __ldg(m+0),  m01 = __ldg(m+1),  m02 = __ldg(m+2),  m03 = __ldg(m+3);
    float m10 = __ldg(m+4),  m11 = __ldg(m+5),  m12 = __ldg(m+6),  m13 = __ldg(m+7);
    float m20 = __ldg(m+8),  m21 = __ldg(m+9),  m22 = __ldg(m+10), m23 = __ldg(m+11);

    const float step = 2.0f / 127.0f;
    int i1 = i1t + lane;
    float xn = fmaf((float)i1, step, -1.0f);
    float yn = fmaf((float)i0, step, -1.0f);

    // z-independent parts; fold the (v+1)*64 scale in as fmaf at the end
    float bx = fmaf(m00, xn, fmaf(m01, yn, m03));
    float by = fmaf(m10, xn, fmaf(m11, yn, m13));
    float bz = fmaf(m20, xn, fmaf(m21, yn, m23));

    const float2* __restrict__ vol = (const float2*)images + (size_t)b * R3_;

    int i2base = i2t + (warp << 2);

    #pragma unroll
    for (int jj = 0; jj < 2; jj++) {
        int jA = jj * 2;
        int jB = jA + 1;

        float znA = fmaf((float)(i2base + jA), step, -1.0f);
        float znB = fmaf((float)(i2base + jB), step, -1.0f);

        float xA = fmaf(fmaf(m02, znA, bx), 64.0f, 64.0f);
        float yA = fmaf(fmaf(m12, znA, by), 64.0f, 64.0f);
        float zA = fmaf(fmaf(m22, znA, bz), 64.0f, 64.0f);
        float xB = fmaf(fmaf(m02, znB, bx), 64.0f, 64.0f);
        float yB = fmaf(fmaf(m12, znB, by), 64.0f, 64.0f);
        float zB = fmaf(fmaf(m22, znB, bz), 64.0f, 64.0f);

        Corner A = make_corner(xA, yA, zA);
        Corner B = make_corner(xB, yB, zB);

        // Issue all 16 gathers before any consumption (max MLP)
        float2 a000 = __ldg(vol + A.r00 + A.x0);
        float2 a100 = __ldg(vol + A.r10 + A.x0);
        float2 a010 = __ldg(vol + A.r01 + A.x0);
        float2 a110 = __ldg(vol + A.r11 + A.x0);
        float2 a001 = __ldg(vol + A.r00 + A.x1);
        float2 a101 = __ldg(vol + A.r10 + A.x1);
        float2 a011 = __ldg(vol + A.r01 + A.x1);
        float2 a111 = __ldg(vol + A.r11 + A.x1);

        float2 b000 = __ldg(vol + B.r00 + B.x0);
        float2 b100 = __ldg(vol + B.r10 + B.x0);
        float2 b010 = __ldg(vol + B.r01 + B.x0);
        float2 b110 = __ldg(vol + B.r11 + B.x0);
        float2 b001 = __ldg(vol + B.r00 + B.x1);
        float2 b101 = __ldg(vol + B.r10 + B.x1);
        float2 b011 = __ldg(vol + B.r01 + B.x1);
        float2 b111 = __ldg(vol + B.r11 + B.x1);

        tile[(warp << 2) + jA][lane] =
            lerp8(A, a000, a001, a010, a011, a100, a101, a110, a111);
        tile[(warp << 2) + jB][lane] =
            lerp8(B, b000, b001, b010, b011, b100, b101, b110, b111);
    }

    __syncthreads();

    size_t out_base = ((size_t)b << 21) + ((size_t)i0 << 14);
    #pragma unroll
    for (int j = 0; j < 4; j++) {
        int i1l = warp + (j << 3);
        float2 v = tile[lane][i1l];
        out[out_base + (size_t)(i1t + i1l) * 128 + (i2t + lane)] = v;
    }
}

extern "C" void kernel_launch(void* const* d_in, const int* in_sizes, int n_in,
                              void* d_out, int out_size)
{
    const float* images = (const float*)d_in[0];
    const float* params = (const float*)d_in[1];
    float2* out = (float2*)d_out;

    st3d_kernel<<<8192, 256>>>(images, params, out);
}